// round 1
// baseline (speedup 1.0000x reference)
#include <cuda_runtime.h>

// Problem constants (fixed shapes)
#define BB 16384
#define DD 2048
#define HH 1024
#define EE 16
#define KTAIL 16      // E appended features into routing net
#define TOPC 409      // int(0.2 * 2048)

// Scratch (device globals; no runtime allocation allowed)
__device__ float g_h1[(size_t)BB * HH];
__device__ float g_h2[(size_t)BB * HH];
__device__ float g_spec[(size_t)BB * EE];
__device__ int   g_cnt[3];
__device__ int   g_k;

// ---------------------------------------------------------------------------
// block-wide reduction helper (256 threads)
// ---------------------------------------------------------------------------
__device__ __forceinline__ float block_reduce(float v, float* red, bool ismax)
{
    int tid = threadIdx.x;
#pragma unroll
    for (int o = 16; o; o >>= 1) {
        float t = __shfl_down_sync(0xffffffffu, v, o);
        v = ismax ? fmaxf(v, t) : (v + t);
    }
    if ((tid & 31) == 0) red[tid >> 5] = v;
    __syncthreads();
    if (tid < 32) {
        float t2 = (tid < 8) ? red[tid] : (ismax ? -3.4e38f : 0.0f);
#pragma unroll
        for (int o = 4; o; o >>= 1) {
            float t = __shfl_down_sync(0xffffffffu, t2, o);
            t2 = ismax ? fmaxf(t2, t) : (t2 + t);
        }
        if (tid == 0) red[0] = t2;
    }
    __syncthreads();
    float r = red[0];
    __syncthreads();
    return r;
}

// ---------------------------------------------------------------------------
// Stats kernel: one block per row. mean/var/skew/max/norm/zeros + top-409 sum
// via in-smem bitonic sort of |x|.
// ---------------------------------------------------------------------------
__global__ void stats_kernel(const float* __restrict__ x, float* __restrict__ stats)
{
    __shared__ float sx[2048];
    __shared__ float red[8];
    int row = blockIdx.x;
    int tid = threadIdx.x;

    const float4* xr = (const float4*)(x + (size_t)row * DD);
    float4* sx4 = (float4*)sx;
    for (int i = tid; i < 512; i += 256) sx4[i] = xr[i];
    __syncthreads();

    float sum = 0.f, sumsq = 0.f, maxa = 0.f, suma = 0.f, zc = 0.f;
    for (int i = tid; i < 2048; i += 256) {
        float v = sx[i];
        sum += v; sumsq += v * v;
        float a = fabsf(v);
        suma += a; maxa = fmaxf(maxa, a);
        zc += (v == 0.0f) ? 1.f : 0.f;
    }
    sum   = block_reduce(sum,   red, false);
    sumsq = block_reduce(sumsq, red, false);
    suma  = block_reduce(suma,  red, false);
    zc    = block_reduce(zc,    red, false);
    maxa  = block_reduce(maxa,  red, true);

    float mean = sum * (1.0f / 2048.0f);

    // two-pass variance + skew numerator
    float s2 = 0.f, s3 = 0.f;
    for (int i = tid; i < 2048; i += 256) {
        float d = sx[i] - mean;
        s2 += d * d;
        s3 += d * d * d;
    }
    s2 = block_reduce(s2, red, false);
    s3 = block_reduce(s3, red, false);

    float var  = s2 * (1.0f / 2047.0f);
    float stdv = sqrtf(var + 1e-8f);
    float skew = (s3 * (1.0f / 2048.0f)) / (stdv * stdv * stdv);

    // |x| in place, ascending bitonic sort, sum of last TOPC elements
    for (int i = tid; i < 2048; i += 256) sx[i] = fabsf(sx[i]);

    for (int size = 2; size <= 2048; size <<= 1) {
        for (int stride = size >> 1; stride > 0; stride >>= 1) {
            __syncthreads();
            for (int t = tid; t < 1024; t += 256) {
                int q = t / stride;
                int r = t - q * stride;
                int lo = q * (stride << 1) + r;
                int hi = lo + stride;
                bool up = ((lo & size) == 0);
                float a = sx[lo], b = sx[hi];
                if ((a > b) == up) { sx[lo] = b; sx[hi] = a; }
            }
        }
    }
    __syncthreads();

    float tsum = 0.f;
    for (int i = 2048 - TOPC + tid; i < 2048; i += 256) tsum += sx[i];
    tsum = block_reduce(tsum, red, false);

    if (tid == 0) {
        float* o = stats + (size_t)row * 6;
        o[0] = zc * (1.0f / 2048.0f);       // sparsity
        o[1] = var;                          // variance (unbiased)
        o[2] = maxa;                         // magnitude
        o[3] = sqrtf(sumsq);                 // norm
        o[4] = skew;                         // skewness
        o[5] = tsum / (suma + 1e-8f);        // concentration
    }
}

// ---------------------------------------------------------------------------
// SGEMM: C[M,N] = relu(A[M,K]@W[K,N] (+ A2[M,K2]@W2[K2,N]) + bias)
// 128x128 tile, BK=8, 256 threads, 8x8 per thread, double-buffered smem.
// M%128==0, N%128==0, K%8==0, K2%8==0 assumed.
// ---------------------------------------------------------------------------
__global__ __launch_bounds__(256, 2)
void sgemm_relu(const float* __restrict__ A, const float* __restrict__ W,
                const float* __restrict__ bias,
                const float* __restrict__ A2, const float* __restrict__ W2,
                int K, int K2, int N, float* __restrict__ C)
{
    __shared__ float As[2][8][132];
    __shared__ float Bs[2][8][128];

    int tid = threadIdx.x;
    int m0 = blockIdx.y * 128;
    int n0 = blockIdx.x * 128;

    int lr = tid >> 1;            // A tile row 0..127
    int lc = (tid & 1) * 4;       // A tile col {0,4}
    int wr = tid >> 5;            // W tile row 0..7
    int wc = (tid & 31) * 4;      // W tile col

    int nk = (K + K2) >> 3;

    // preload tile 0 (always within primary K)
    {
        float4 ra = *(const float4*)(A + (size_t)(m0 + lr) * K + lc);
        float4 rb = *(const float4*)(W + (size_t)wr * N + n0 + wc);
        As[0][lc + 0][lr] = ra.x; As[0][lc + 1][lr] = ra.y;
        As[0][lc + 2][lr] = ra.z; As[0][lc + 3][lr] = ra.w;
        *(float4*)&Bs[0][wr][wc] = rb;
    }
    __syncthreads();

    float acc[8][8] = {};
    int ty = tid >> 4, tx = tid & 15;

    for (int t = 0; t < nk; ++t) {
        int buf = t & 1;
        bool pre = (t + 1 < nk);
        float4 ra, rb;
        if (pre) {
            int kb = (t + 1) << 3;
            if (kb < K) {
                ra = *(const float4*)(A + (size_t)(m0 + lr) * K + kb + lc);
                rb = *(const float4*)(W + (size_t)(kb + wr) * N + n0 + wc);
            } else {
                int kb2 = kb - K;
                ra = *(const float4*)(A2 + (size_t)(m0 + lr) * K2 + kb2 + lc);
                rb = *(const float4*)(W2 + (size_t)(kb2 + wr) * N + n0 + wc);
            }
        }
#pragma unroll
        for (int k = 0; k < 8; ++k) {
            float a[8], b[8];
            *(float4*)(a)     = *(float4*)&As[buf][k][ty * 8];
            *(float4*)(a + 4) = *(float4*)&As[buf][k][ty * 8 + 4];
            *(float4*)(b)     = *(float4*)&Bs[buf][k][tx * 8];
            *(float4*)(b + 4) = *(float4*)&Bs[buf][k][tx * 8 + 4];
#pragma unroll
            for (int i = 0; i < 8; ++i)
#pragma unroll
                for (int j = 0; j < 8; ++j)
                    acc[i][j] += a[i] * b[j];
        }
        if (pre) {
            int nb = buf ^ 1;
            As[nb][lc + 0][lr] = ra.x; As[nb][lc + 1][lr] = ra.y;
            As[nb][lc + 2][lr] = ra.z; As[nb][lc + 3][lr] = ra.w;
            *(float4*)&Bs[nb][wr][wc] = rb;
        }
        __syncthreads();
    }

    float bv[8];
    *(float4*)(bv)     = *(const float4*)(bias + n0 + tx * 8);
    *(float4*)(bv + 4) = *(const float4*)(bias + n0 + tx * 8 + 4);
#pragma unroll
    for (int i = 0; i < 8; ++i) {
        size_t base = (size_t)(m0 + ty * 8 + i) * N + n0 + tx * 8;
        float4 o;
        o.x = fmaxf(acc[i][0] + bv[0], 0.f); o.y = fmaxf(acc[i][1] + bv[1], 0.f);
        o.z = fmaxf(acc[i][2] + bv[2], 0.f); o.w = fmaxf(acc[i][3] + bv[3], 0.f);
        *(float4*)(C + base) = o;
        o.x = fmaxf(acc[i][4] + bv[4], 0.f); o.y = fmaxf(acc[i][5] + bv[5], 0.f);
        o.z = fmaxf(acc[i][6] + bv[6], 0.f); o.w = fmaxf(acc[i][7] + bv[7], 0.f);
        *(float4*)(C + base + 4) = o;
    }
}

// ---------------------------------------------------------------------------
// spec kernel: spec = sigmoid(x@patterns^T + h1@Ws2 + bs2)
// 64 rows/block, 256 threads: thread owns 4 rows x 1 expert.
// ---------------------------------------------------------------------------
__global__ void spec_kernel(const float* __restrict__ x, const float* __restrict__ pat,
                            const float* __restrict__ h1, const float* __restrict__ Ws2,
                            const float* __restrict__ bs2, float* __restrict__ spec)
{
    __shared__ float xs[64][68];
    __shared__ float ws[64][16];
    int tid = threadIdx.x;
    int row0 = blockIdx.x * 64;
    int e = tid & 15;
    int r0 = (tid >> 4) * 4;
    float acc[4] = {};

    // phase 1: sims = x @ patterns^T  (K = 2048, pat is [16][2048])
    for (int kc = 0; kc < DD; kc += 64) {
#pragma unroll
        for (int it = 0; it < 4; ++it) {
            int idx = tid + it * 256;
            int r = idx >> 4, c4 = idx & 15;
            *(float4*)&xs[r][c4 * 4] =
                *(const float4*)(x + (size_t)(row0 + r) * DD + kc + c4 * 4);
        }
        {
            int pe = tid & 15, k4 = tid >> 4;
            float4 v = *(const float4*)(pat + (size_t)pe * DD + kc + k4 * 4);
            ws[k4 * 4 + 0][pe] = v.x; ws[k4 * 4 + 1][pe] = v.y;
            ws[k4 * 4 + 2][pe] = v.z; ws[k4 * 4 + 3][pe] = v.w;
        }
        __syncthreads();
#pragma unroll 4
        for (int k = 0; k < 64; ++k) {
            float w = ws[k][e];
            acc[0] += xs[r0 + 0][k] * w;
            acc[1] += xs[r0 + 1][k] * w;
            acc[2] += xs[r0 + 2][k] * w;
            acc[3] += xs[r0 + 3][k] * w;
        }
        __syncthreads();
    }
    // phase 2: h1 @ Ws2  (K = 1024, Ws2 is [1024][16])
    for (int kc = 0; kc < HH; kc += 64) {
#pragma unroll
        for (int it = 0; it < 4; ++it) {
            int idx = tid + it * 256;
            int r = idx >> 4, c4 = idx & 15;
            *(float4*)&xs[r][c4 * 4] =
                *(const float4*)(h1 + (size_t)(row0 + r) * HH + kc + c4 * 4);
        }
        {
            int k = tid >> 2, e4 = tid & 3;
            *(float4*)&ws[k][e4 * 4] =
                *(const float4*)(Ws2 + (size_t)(kc + k) * EE + e4 * 4);
        }
        __syncthreads();
#pragma unroll 4
        for (int k = 0; k < 64; ++k) {
            float w = ws[k][e];
            acc[0] += xs[r0 + 0][k] * w;
            acc[1] += xs[r0 + 1][k] * w;
            acc[2] += xs[r0 + 2][k] * w;
            acc[3] += xs[r0 + 3][k] * w;
        }
        __syncthreads();
    }
    float b = bs2[e];
#pragma unroll
    for (int j = 0; j < 4; ++j) {
        float v = acc[j] + b;
        spec[(size_t)(row0 + r0 + j) * EE + e] = 1.0f / (1.0f + expf(-v));
    }
}

// ---------------------------------------------------------------------------
// probs kernel: probs = softmax(h2 @ Wr2 + br2)
// ---------------------------------------------------------------------------
__global__ void probs_kernel(const float* __restrict__ h2, const float* __restrict__ Wr2,
                             const float* __restrict__ br2, float* __restrict__ probs)
{
    __shared__ float xs[64][68];
    __shared__ float ws[64][16];
    __shared__ float lg[64][17];
    int tid = threadIdx.x;
    int row0 = blockIdx.x * 64;
    int e = tid & 15;
    int r0 = (tid >> 4) * 4;
    float acc[4] = {};

    for (int kc = 0; kc < HH; kc += 64) {
#pragma unroll
        for (int it = 0; it < 4; ++it) {
            int idx = tid + it * 256;
            int r = idx >> 4, c4 = idx & 15;
            *(float4*)&xs[r][c4 * 4] =
                *(const float4*)(h2 + (size_t)(row0 + r) * HH + kc + c4 * 4);
        }
        {
            int k = tid >> 2, e4 = tid & 3;
            *(float4*)&ws[k][e4 * 4] =
                *(const float4*)(Wr2 + (size_t)(kc + k) * EE + e4 * 4);
        }
        __syncthreads();
#pragma unroll 4
        for (int k = 0; k < 64; ++k) {
            float w = ws[k][e];
            acc[0] += xs[r0 + 0][k] * w;
            acc[1] += xs[r0 + 1][k] * w;
            acc[2] += xs[r0 + 2][k] * w;
            acc[3] += xs[r0 + 3][k] * w;
        }
        __syncthreads();
    }
    float b = br2[e];
#pragma unroll
    for (int j = 0; j < 4; ++j) lg[r0 + j][e] = acc[j] + b;
    __syncthreads();

    if (tid < 64) {
        int r = tid;
        float m = -3.4e38f;
#pragma unroll
        for (int k = 0; k < 16; ++k) m = fmaxf(m, lg[r][k]);
        float pv[16]; float s = 0.f;
#pragma unroll
        for (int k = 0; k < 16; ++k) { pv[k] = expf(lg[r][k] - m); s += pv[k]; }
        float inv = 1.0f / s;
        float* o = probs + (size_t)(row0 + r) * EE;
#pragma unroll
        for (int k = 0; k < 16; ++k) o[k] = pv[k] * inv;
    }
}

// ---------------------------------------------------------------------------
// k predictor: per-row tiny MLP + warp-aggregated counts for median
// ---------------------------------------------------------------------------
__global__ void kpred_kernel(const float* __restrict__ stats, const float* __restrict__ Wk1,
                             const float* __restrict__ bk1, const float* __restrict__ Wk2,
                             const float* __restrict__ bk2)
{
    int row = blockIdx.x * 256 + threadIdx.x;
    float s[6];
#pragma unroll
    for (int i = 0; i < 6; ++i) s[i] = stats[(size_t)row * 6 + i];
    float o = bk2[0];
#pragma unroll
    for (int h = 0; h < 16; ++h) {
        float z = bk1[h];
#pragma unroll
        for (int i = 0; i < 6; ++i) z += s[i] * Wk1[i * 16 + h];
        o += fmaxf(z, 0.f) * Wk2[h];
    }
    float kv = 1.0f / (1.0f + expf(-o));
    float val = 1.0f + 3.0f * kv;
    unsigned b2 = __ballot_sync(0xffffffffu, val < 2.0f);
    unsigned b3 = __ballot_sync(0xffffffffu, val < 3.0f);
    unsigned b4 = __ballot_sync(0xffffffffu, val < 4.0f);
    if ((threadIdx.x & 31) == 0) {
        atomicAdd(&g_cnt[0], __popc(b2));
        atomicAdd(&g_cnt[1], __popc(b3));
        atomicAdd(&g_cnt[2], __popc(b4));
    }
}

__global__ void init_kernel() { g_cnt[0] = 0; g_cnt[1] = 0; g_cnt[2] = 0; }

__global__ void kdecide_kernel()
{
    // lower median position = 8191 (0-based) of 16384; floor(median) from counts
    int k;
    if (g_cnt[0] >= 8192)      k = 1;
    else if (g_cnt[1] >= 8192) k = 2;
    else if (g_cnt[2] >= 8192) k = 3;
    else                       k = 4;
    g_k = k;
}

// ---------------------------------------------------------------------------
// top-k + gates: one thread per row. jax.lax.top_k tie-break = lowest index.
// ---------------------------------------------------------------------------
__global__ void topk_kernel(const float* __restrict__ probs,
                            float* __restrict__ gates, float* __restrict__ idxo)
{
    int row = blockIdx.x * 256 + threadIdx.x;
    float p[16];
    const float4* pr = (const float4*)(probs + (size_t)row * EE);
    ((float4*)p)[0] = pr[0]; ((float4*)p)[1] = pr[1];
    ((float4*)p)[2] = pr[2]; ((float4*)p)[3] = pr[3];

    unsigned used = 0;
    float tv[4]; int ti[4];
#pragma unroll
    for (int s = 0; s < 4; ++s) {
        float bv = -1.0f; int bi = 0;
#pragma unroll
        for (int e = 0; e < 16; ++e) {
            bool ok = (((used >> e) & 1u) == 0u) && (p[e] > bv);
            if (ok) { bv = p[e]; bi = e; }
        }
        used |= (1u << bi);
        tv[s] = bv; ti[s] = bi;
    }
    int k = g_k;
    float g[4]; float ssum = 0.f;
#pragma unroll
    for (int j = 0; j < 4; ++j) {
        g[j] = (j < k) ? expf(tv[j] - tv[0]) : 0.0f;
        ssum += g[j];
    }
    float inv = 1.0f / ssum;
#pragma unroll
    for (int j = 0; j < 4; ++j) {
        gates[(size_t)row * 4 + j] = g[j] * inv;
        idxo[(size_t)row * 4 + j] = (float)ti[j];
    }
}

// ---------------------------------------------------------------------------
extern "C" void kernel_launch(void* const* d_in, const int* in_sizes, int n_in,
                              void* d_out, int out_size)
{
    const float* x    = (const float*)d_in[0];
    const float* pat  = (const float*)d_in[1];
    const float* Ws1  = (const float*)d_in[2];
    const float* bs1  = (const float*)d_in[3];
    const float* Ws2  = (const float*)d_in[4];
    const float* bs2  = (const float*)d_in[5];
    const float* Wr1  = (const float*)d_in[6];
    const float* br1  = (const float*)d_in[7];
    const float* Wr2  = (const float*)d_in[8];
    const float* br2  = (const float*)d_in[9];
    const float* Wk1  = (const float*)d_in[10];
    const float* bk1  = (const float*)d_in[11];
    const float* Wk2  = (const float*)d_in[12];
    const float* bk2  = (const float*)d_in[13];

    float* out = (float*)d_out;
    float* o_gates = out;                      // 16384*4
    float* o_idx   = out + 65536;              // 16384*4
    float* o_probs = out + 131072;             // 16384*16
    float* o_stats = out + 393216;             // 16384*6

    void *p_h1 = nullptr, *p_h2 = nullptr, *p_spec = nullptr;
    cudaGetSymbolAddress(&p_h1, g_h1);
    cudaGetSymbolAddress(&p_h2, g_h2);
    cudaGetSymbolAddress(&p_spec, g_spec);
    float* h1 = (float*)p_h1;
    float* h2 = (float*)p_h2;
    float* spec = (float*)p_spec;

    // stats + dynamic-k chain
    stats_kernel<<<BB, 256>>>(x, o_stats);
    init_kernel<<<1, 1>>>();
    kpred_kernel<<<BB / 256, 256>>>(o_stats, Wk1, bk1, Wk2, bk2);
    kdecide_kernel<<<1, 1>>>();

    // similarity network hidden: h1 = relu(x @ Ws1 + bs1)
    dim3 gg(HH / 128, BB / 128);
    sgemm_relu<<<gg, 256>>>(x, Ws1, bs1, nullptr, nullptr, DD, 0, HH, h1);

    // spec_scores = sigmoid(x@pat^T + h1@Ws2 + bs2)
    spec_kernel<<<BB / 64, 256>>>(x, pat, h1, Ws2, bs2, spec);

    // routing hidden: h2 = relu(x@Wr1[:2048] + spec@Wr1[2048:2064] + br1)
    sgemm_relu<<<gg, 256>>>(x, Wr1, br1, spec, Wr1 + (size_t)DD * HH, DD, KTAIL, HH, h2);

    // probs = softmax(h2 @ Wr2 + br2)
    probs_kernel<<<BB / 64, 256>>>(h2, Wr2, br2, o_probs);

    // gates + indices
    topk_kernel<<<BB / 256, 256>>>(o_probs, o_gates, o_idx);

    (void)in_sizes; (void)n_in; (void)out_size;
}

// round 3
// speedup vs baseline: 1.2428x; 1.2428x over previous
#include <cuda_runtime.h>
#include <cstdint>

// Problem constants (fixed shapes)
#define BB 16384
#define DD 2048
#define HH 1024
#define EE 16
#define TOPC 409

// Scratch (device globals; no runtime allocation allowed)
__device__ float g_h1[(size_t)BB * HH];
__device__ float g_h2[(size_t)BB * HH];
__device__ float g_spec[(size_t)BB * EE];
__device__ int   g_cnt[3];
__device__ int   g_k;

// ---------------------------------------------------------------------------
// block-wide reduction helper (256 threads)
// ---------------------------------------------------------------------------
__device__ __forceinline__ float block_reduce(float v, float* red, bool ismax)
{
    int tid = threadIdx.x;
#pragma unroll
    for (int o = 16; o; o >>= 1) {
        float t = __shfl_down_sync(0xffffffffu, v, o);
        v = ismax ? fmaxf(v, t) : (v + t);
    }
    if ((tid & 31) == 0) red[tid >> 5] = v;
    __syncthreads();
    if (tid < 32) {
        float t2 = (tid < 8) ? red[tid] : (ismax ? -3.4e38f : 0.0f);
#pragma unroll
        for (int o = 4; o; o >>= 1) {
            float t = __shfl_down_sync(0xffffffffu, t2, o);
            t2 = ismax ? fmaxf(t2, t) : (t2 + t);
        }
        if (tid == 0) red[0] = t2;
    }
    __syncthreads();
    float r = red[0];
    __syncthreads();
    return r;
}

// ---------------------------------------------------------------------------
// Stats kernel: moments + exact top-409 |x| sum via 4-pass radix select
// ---------------------------------------------------------------------------
__global__ void stats_kernel(const float* __restrict__ x, float* __restrict__ stats)
{
    __shared__ float sx[2048];
    __shared__ float red[8];
    __shared__ int hist[256];
    __shared__ int scan[256];
    __shared__ unsigned s_pref;
    __shared__ int s_need;

    int row = blockIdx.x;
    int tid = threadIdx.x;

    const float4* xr = (const float4*)(x + (size_t)row * DD);
    float4* sx4 = (float4*)sx;
    for (int i = tid; i < 512; i += 256) sx4[i] = xr[i];
    __syncthreads();

    float sum = 0.f, sumsq = 0.f, maxa = 0.f, suma = 0.f, zc = 0.f;
    for (int i = tid; i < 2048; i += 256) {
        float v = sx[i];
        sum += v; sumsq += v * v;
        float a = fabsf(v);
        suma += a; maxa = fmaxf(maxa, a);
        zc += (v == 0.0f) ? 1.f : 0.f;
    }
    sum   = block_reduce(sum,   red, false);
    sumsq = block_reduce(sumsq, red, false);
    suma  = block_reduce(suma,  red, false);
    zc    = block_reduce(zc,    red, false);
    maxa  = block_reduce(maxa,  red, true);

    float mean = sum * (1.0f / 2048.0f);
    float s2 = 0.f, s3 = 0.f;
    for (int i = tid; i < 2048; i += 256) {
        float d = sx[i] - mean;
        s2 += d * d;
        s3 += d * d * d;
    }
    s2 = block_reduce(s2, red, false);
    s3 = block_reduce(s3, red, false);
    float var  = s2 * (1.0f / 2047.0f);
    float stdv = sqrtf(var + 1e-8f);
    float skew = (s3 * (1.0f / 2048.0f)) / (stdv * stdv * stdv);

    // radix select on |x| bits (monotone for non-negative floats)
    unsigned prefix = 0;
    int need = TOPC;
#pragma unroll
    for (int pass = 0; pass < 4; ++pass) {
        int shift = 24 - 8 * pass;
        hist[tid] = 0;
        __syncthreads();
        for (int i = tid; i < 2048; i += 256) {
            unsigned b = __float_as_uint(sx[i]) & 0x7fffffffu;
            bool match = (pass == 0) || ((b >> (shift + 8)) == prefix);
            if (match) atomicAdd(&hist[(b >> shift) & 255], 1);
        }
        __syncthreads();
        scan[tid] = hist[tid];
        __syncthreads();
        for (int off = 1; off < 256; off <<= 1) {
            int v2 = (tid + off < 256) ? scan[tid + off] : 0;
            __syncthreads();
            scan[tid] += v2;
            __syncthreads();
        }
        int incl = scan[tid];            // count of matched values with byte >= tid
        int excl = incl - hist[tid];     // count with byte > tid
        if (excl < need && need <= incl) {
            s_pref = (prefix << 8) | (unsigned)tid;
            s_need = need - excl;
        }
        __syncthreads();
        prefix = s_pref;
        need = s_need;
        __syncthreads();
    }

    unsigned tb = prefix;
    float tval = __uint_as_float(tb);
    float tsum = 0.f;
    for (int i = tid; i < 2048; i += 256) {
        unsigned b = __float_as_uint(sx[i]) & 0x7fffffffu;
        if (b > tb) tsum += __uint_as_float(b);
    }
    tsum = block_reduce(tsum, red, false);
    tsum += (float)need * tval;

    if (tid == 0) {
        float* o = stats + (size_t)row * 6;
        o[0] = zc * (1.0f / 2048.0f);
        o[1] = var;
        o[2] = maxa;
        o[3] = sqrtf(sumsq);
        o[4] = skew;
        o[5] = tsum / (suma + 1e-8f);
    }
}

// ---------------------------------------------------------------------------
// SGEMM with packed f32x2 FMA:
// C[M,N] = relu(A[M,K]@W[K,N] (+ A2[M,K2]@W2[K2,N]) + bias)
// 128x128 tile, BK=8, 256 threads, 8x8 per thread, double-buffered smem.
// ---------------------------------------------------------------------------
__global__ __launch_bounds__(256, 2)
void sgemm_relu(const float* __restrict__ A, const float* __restrict__ W,
                const float* __restrict__ bias,
                const float* __restrict__ A2, const float* __restrict__ W2,
                int K, int K2, int N, float* __restrict__ C)
{
    __shared__ float As[2][8][132];
    __shared__ float Bs[2][8][128];

    int tid = threadIdx.x;
    int m0 = blockIdx.y * 128;
    int n0 = blockIdx.x * 128;

    int lr = tid >> 1;            // A tile row 0..127
    int lc = (tid & 1) * 4;       // A tile col {0,4}
    int wr = tid >> 5;            // W tile row 0..7
    int wc = (tid & 31) * 4;      // W tile col

    int nk = (K + K2) >> 3;

    {
        float4 ra = *(const float4*)(A + (size_t)(m0 + lr) * K + lc);
        float4 rb = *(const float4*)(W + (size_t)wr * N + n0 + wc);
        As[0][lc + 0][lr] = ra.x; As[0][lc + 1][lr] = ra.y;
        As[0][lc + 2][lr] = ra.z; As[0][lc + 3][lr] = ra.w;
        *(float4*)&Bs[0][wr][wc] = rb;
    }
    __syncthreads();

    // packed accumulators: acc2[i][j2] holds cols {2*j2, 2*j2+1} of row i
    unsigned long long acc2[8][4] = {};
    int ty = tid >> 4, tx = tid & 15;

    for (int t = 0; t < nk; ++t) {
        int buf = t & 1;
        bool pre = (t + 1 < nk);
        float4 ra, rb;
        if (pre) {
            int kb = (t + 1) << 3;
            if (kb < K) {
                ra = *(const float4*)(A + (size_t)(m0 + lr) * K + kb + lc);
                rb = *(const float4*)(W + (size_t)(kb + wr) * N + n0 + wc);
            } else {
                int kb2 = kb - K;
                ra = *(const float4*)(A2 + (size_t)(m0 + lr) * K2 + kb2 + lc);
                rb = *(const float4*)(W2 + (size_t)(kb2 + wr) * N + n0 + wc);
            }
        }
#pragma unroll
        for (int k = 0; k < 8; ++k) {
            float a[8];
            *(float4*)(a)     = *(float4*)&As[buf][k][ty * 8];
            *(float4*)(a + 4) = *(float4*)&As[buf][k][ty * 8 + 4];
            // b pairs: 4 packed f32x2 values (consecutive cols)
            ulonglong2 b01 = *(ulonglong2*)&Bs[buf][k][tx * 8];
            ulonglong2 b23 = *(ulonglong2*)&Bs[buf][k][tx * 8 + 4];
#pragma unroll
            for (int i = 0; i < 8; ++i) {
                unsigned long long da;
                asm("mov.b64 %0, {%1, %1};" : "=l"(da) : "r"(__float_as_uint(a[i])));
                asm("fma.rn.f32x2 %0, %1, %2, %0;" : "+l"(acc2[i][0]) : "l"(da), "l"(b01.x));
                asm("fma.rn.f32x2 %0, %1, %2, %0;" : "+l"(acc2[i][1]) : "l"(da), "l"(b01.y));
                asm("fma.rn.f32x2 %0, %1, %2, %0;" : "+l"(acc2[i][2]) : "l"(da), "l"(b23.x));
                asm("fma.rn.f32x2 %0, %1, %2, %0;" : "+l"(acc2[i][3]) : "l"(da), "l"(b23.y));
            }
        }
        if (pre) {
            int nb = buf ^ 1;
            As[nb][lc + 0][lr] = ra.x; As[nb][lc + 1][lr] = ra.y;
            As[nb][lc + 2][lr] = ra.z; As[nb][lc + 3][lr] = ra.w;
            *(float4*)&Bs[nb][wr][wc] = rb;
        }
        __syncthreads();
    }

    float bv[8];
    *(float4*)(bv)     = *(const float4*)(bias + n0 + tx * 8);
    *(float4*)(bv + 4) = *(const float4*)(bias + n0 + tx * 8 + 4);
#pragma unroll
    for (int i = 0; i < 8; ++i) {
        size_t base = (size_t)(m0 + ty * 8 + i) * N + n0 + tx * 8;
        float c[8];
#pragma unroll
        for (int j2 = 0; j2 < 4; ++j2) {
            unsigned long long v = acc2[i][j2];
            c[2 * j2]     = __uint_as_float((unsigned)(v & 0xffffffffu));
            c[2 * j2 + 1] = __uint_as_float((unsigned)(v >> 32));
        }
        float4 o;
        o.x = fmaxf(c[0] + bv[0], 0.f); o.y = fmaxf(c[1] + bv[1], 0.f);
        o.z = fmaxf(c[2] + bv[2], 0.f); o.w = fmaxf(c[3] + bv[3], 0.f);
        *(float4*)(C + base) = o;
        o.x = fmaxf(c[4] + bv[4], 0.f); o.y = fmaxf(c[5] + bv[5], 0.f);
        o.z = fmaxf(c[6] + bv[6], 0.f); o.w = fmaxf(c[7] + bv[7], 0.f);
        *(float4*)(C + base + 4) = o;
    }
}

// ---------------------------------------------------------------------------
// spec kernel: spec = sigmoid(x@patterns^T + h1@Ws2 + bs2)
// ---------------------------------------------------------------------------
__global__ void spec_kernel(const float* __restrict__ x, const float* __restrict__ pat,
                            const float* __restrict__ h1, const float* __restrict__ Ws2,
                            const float* __restrict__ bs2, float* __restrict__ spec)
{
    __shared__ float xs[64][68];
    __shared__ float ws[64][16];
    int tid = threadIdx.x;
    int row0 = blockIdx.x * 64;
    int e = tid & 15;
    int r0 = (tid >> 4) * 4;
    float acc[4] = {};

    for (int kc = 0; kc < DD; kc += 64) {
#pragma unroll
        for (int it = 0; it < 4; ++it) {
            int idx = tid + it * 256;
            int r = idx >> 4, c4 = idx & 15;
            *(float4*)&xs[r][c4 * 4] =
                *(const float4*)(x + (size_t)(row0 + r) * DD + kc + c4 * 4);
        }
        {
            int pe = tid & 15, k4 = tid >> 4;
            float4 v = *(const float4*)(pat + (size_t)pe * DD + kc + k4 * 4);
            ws[k4 * 4 + 0][pe] = v.x; ws[k4 * 4 + 1][pe] = v.y;
            ws[k4 * 4 + 2][pe] = v.z; ws[k4 * 4 + 3][pe] = v.w;
        }
        __syncthreads();
#pragma unroll 4
        for (int k = 0; k < 64; ++k) {
            float w = ws[k][e];
            acc[0] += xs[r0 + 0][k] * w;
            acc[1] += xs[r0 + 1][k] * w;
            acc[2] += xs[r0 + 2][k] * w;
            acc[3] += xs[r0 + 3][k] * w;
        }
        __syncthreads();
    }
    for (int kc = 0; kc < HH; kc += 64) {
#pragma unroll
        for (int it = 0; it < 4; ++it) {
            int idx = tid + it * 256;
            int r = idx >> 4, c4 = idx & 15;
            *(float4*)&xs[r][c4 * 4] =
                *(const float4*)(h1 + (size_t)(row0 + r) * HH + kc + c4 * 4);
        }
        {
            int k = tid >> 2, e4 = tid & 3;
            *(float4*)&ws[k][e4 * 4] =
                *(const float4*)(Ws2 + (size_t)(kc + k) * EE + e4 * 4);
        }
        __syncthreads();
#pragma unroll 4
        for (int k = 0; k < 64; ++k) {
            float w = ws[k][e];
            acc[0] += xs[r0 + 0][k] * w;
            acc[1] += xs[r0 + 1][k] * w;
            acc[2] += xs[r0 + 2][k] * w;
            acc[3] += xs[r0 + 3][k] * w;
        }
        __syncthreads();
    }
    float b = bs2[e];
#pragma unroll
    for (int j = 0; j < 4; ++j) {
        float v = acc[j] + b;
        spec[(size_t)(row0 + r0 + j) * EE + e] = 1.0f / (1.0f + expf(-v));
    }
}

// ---------------------------------------------------------------------------
// probs kernel: probs = softmax(h2 @ Wr2 + br2)
// ---------------------------------------------------------------------------
__global__ void probs_kernel(const float* __restrict__ h2, const float* __restrict__ Wr2,
                             const float* __restrict__ br2, float* __restrict__ probs)
{
    __shared__ float xs[64][68];
    __shared__ float ws[64][16];
    __shared__ float lg[64][17];
    int tid = threadIdx.x;
    int row0 = blockIdx.x * 64;
    int e = tid & 15;
    int r0 = (tid >> 4) * 4;
    float acc[4] = {};

    for (int kc = 0; kc < HH; kc += 64) {
#pragma unroll
        for (int it = 0; it < 4; ++it) {
            int idx = tid + it * 256;
            int r = idx >> 4, c4 = idx & 15;
            *(float4*)&xs[r][c4 * 4] =
                *(const float4*)(h2 + (size_t)(row0 + r) * HH + kc + c4 * 4);
        }
        {
            int k = tid >> 2, e4 = tid & 3;
            *(float4*)&ws[k][e4 * 4] =
                *(const float4*)(Wr2 + (size_t)(kc + k) * EE + e4 * 4);
        }
        __syncthreads();
#pragma unroll 4
        for (int k = 0; k < 64; ++k) {
            float w = ws[k][e];
            acc[0] += xs[r0 + 0][k] * w;
            acc[1] += xs[r0 + 1][k] * w;
            acc[2] += xs[r0 + 2][k] * w;
            acc[3] += xs[r0 + 3][k] * w;
        }
        __syncthreads();
    }
    float b = br2[e];
#pragma unroll
    for (int j = 0; j < 4; ++j) lg[r0 + j][e] = acc[j] + b;
    __syncthreads();

    if (tid < 64) {
        int r = tid;
        float m = -3.4e38f;
#pragma unroll
        for (int k = 0; k < 16; ++k) m = fmaxf(m, lg[r][k]);
        float pv[16]; float s = 0.f;
#pragma unroll
        for (int k = 0; k < 16; ++k) { pv[k] = expf(lg[r][k] - m); s += pv[k]; }
        float inv = 1.0f / s;
        float* o = probs + (size_t)(row0 + r) * EE;
#pragma unroll
        for (int k = 0; k < 16; ++k) o[k] = pv[k] * inv;
    }
}

// ---------------------------------------------------------------------------
// k predictor + median decision
// ---------------------------------------------------------------------------
__global__ void kpred_kernel(const float* __restrict__ stats, const float* __restrict__ Wk1,
                             const float* __restrict__ bk1, const float* __restrict__ Wk2,
                             const float* __restrict__ bk2)
{
    int row = blockIdx.x * 256 + threadIdx.x;
    float s[6];
#pragma unroll
    for (int i = 0; i < 6; ++i) s[i] = stats[(size_t)row * 6 + i];
    float o = bk2[0];
#pragma unroll
    for (int h = 0; h < 16; ++h) {
        float z = bk1[h];
#pragma unroll
        for (int i = 0; i < 6; ++i) z += s[i] * Wk1[i * 16 + h];
        o += fmaxf(z, 0.f) * Wk2[h];
    }
    float kv = 1.0f / (1.0f + expf(-o));
    float val = 1.0f + 3.0f * kv;
    unsigned b2 = __ballot_sync(0xffffffffu, val < 2.0f);
    unsigned b3 = __ballot_sync(0xffffffffu, val < 3.0f);
    unsigned b4 = __ballot_sync(0xffffffffu, val < 4.0f);
    if ((threadIdx.x & 31) == 0) {
        atomicAdd(&g_cnt[0], __popc(b2));
        atomicAdd(&g_cnt[1], __popc(b3));
        atomicAdd(&g_cnt[2], __popc(b4));
    }
}

__global__ void init_kernel() { g_cnt[0] = 0; g_cnt[1] = 0; g_cnt[2] = 0; }

__global__ void kdecide_kernel()
{
    int k;
    if (g_cnt[0] >= 8192)      k = 1;
    else if (g_cnt[1] >= 8192) k = 2;
    else if (g_cnt[2] >= 8192) k = 3;
    else                       k = 4;
    g_k = k;
}

// ---------------------------------------------------------------------------
// top-k + gates
// ---------------------------------------------------------------------------
__global__ void topk_kernel(const float* __restrict__ probs,
                            float* __restrict__ gates, float* __restrict__ idxo)
{
    int row = blockIdx.x * 256 + threadIdx.x;
    float p[16];
    const float4* pr = (const float4*)(probs + (size_t)row * EE);
    ((float4*)p)[0] = pr[0]; ((float4*)p)[1] = pr[1];
    ((float4*)p)[2] = pr[2]; ((float4*)p)[3] = pr[3];

    unsigned used = 0;
    float tv[4]; int ti[4];
#pragma unroll
    for (int s = 0; s < 4; ++s) {
        float bv = -1.0f; int bi = 0;
#pragma unroll
        for (int e = 0; e < 16; ++e) {
            bool ok = (((used >> e) & 1u) == 0u) && (p[e] > bv);
            if (ok) { bv = p[e]; bi = e; }
        }
        used |= (1u << bi);
        tv[s] = bv; ti[s] = bi;
    }
    int k = g_k;
    float g[4]; float ssum = 0.f;
#pragma unroll
    for (int j = 0; j < 4; ++j) {
        g[j] = (j < k) ? expf(tv[j] - tv[0]) : 0.0f;
        ssum += g[j];
    }
    float inv = 1.0f / ssum;
#pragma unroll
    for (int j = 0; j < 4; ++j) {
        gates[(size_t)row * 4 + j] = g[j] * inv;
        idxo[(size_t)row * 4 + j] = (float)ti[j];
    }
}

// ---------------------------------------------------------------------------
extern "C" void kernel_launch(void* const* d_in, const int* in_sizes, int n_in,
                              void* d_out, int out_size)
{
    const float* x    = (const float*)d_in[0];
    const float* pat  = (const float*)d_in[1];
    const float* Ws1  = (const float*)d_in[2];
    const float* bs1  = (const float*)d_in[3];
    const float* Ws2  = (const float*)d_in[4];
    const float* bs2  = (const float*)d_in[5];
    const float* Wr1  = (const float*)d_in[6];
    const float* br1  = (const float*)d_in[7];
    const float* Wr2  = (const float*)d_in[8];
    const float* br2  = (const float*)d_in[9];
    const float* Wk1  = (const float*)d_in[10];
    const float* bk1  = (const float*)d_in[11];
    const float* Wk2  = (const float*)d_in[12];
    const float* bk2  = (const float*)d_in[13];

    float* out = (float*)d_out;
    float* o_gates = out;                      // 16384*4
    float* o_idx   = out + 65536;              // 16384*4
    float* o_probs = out + 131072;             // 16384*16
    float* o_stats = out + 393216;             // 16384*6

    void* p;
    cudaGetSymbolAddress(&p, g_h1);   float* h1 = (float*)p;
    cudaGetSymbolAddress(&p, g_h2);   float* h2 = (float*)p;
    cudaGetSymbolAddress(&p, g_spec); float* spec = (float*)p;

    // stats + dynamic-k chain
    stats_kernel<<<BB, 256>>>(x, o_stats);
    init_kernel<<<1, 1>>>();
    kpred_kernel<<<BB / 256, 256>>>(o_stats, Wk1, bk1, Wk2, bk2);
    kdecide_kernel<<<1, 1>>>();

    // h1 = relu(x @ Ws1 + bs1)
    dim3 gg(HH / 128, BB / 128);
    sgemm_relu<<<gg, 256>>>(x, Ws1, bs1, nullptr, nullptr, DD, 0, HH, h1);

    // spec = sigmoid(x@pat^T + h1@Ws2 + bs2)
    spec_kernel<<<BB / 64, 256>>>(x, pat, h1, Ws2, bs2, spec);

    // h2 = relu(x@Wr1[:2048] + spec@Wr1[2048:2064] + br1)
    sgemm_relu<<<gg, 256>>>(x, Wr1, br1, spec, Wr1 + (size_t)DD * HH, DD, EE, HH, h2);

    // probs = softmax(h2 @ Wr2 + br2)
    probs_kernel<<<BB / 64, 256>>>(h2, Wr2, br2, o_probs);

    // gates + indices
    topk_kernel<<<BB / 256, 256>>>(o_probs, o_gates, o_idx);

    (void)in_sizes; (void)n_in; (void)out_size;
}

// round 4
// speedup vs baseline: 2.7988x; 2.2521x over previous
#include <cuda_runtime.h>
#include <cuda_bf16.h>
#include <cstdint>

// Problem constants (fixed shapes)
#define BB 16384
#define DD 2048
#define HH 1024
#define EE 16
#define TOPC 409
#define KTOT 2080          // padded K for split arrays: 2048 + 16 (spec) + 16 pad, %32==0

// ---------------------------------------------------------------------------
// Device global scratch (no runtime allocation allowed)
// ---------------------------------------------------------------------------
__device__ float g_h1[(size_t)BB * HH];
__device__ float g_h2[(size_t)BB * HH];
__device__ float g_spec[(size_t)BB * EE];
__device__ __nv_bfloat16 g_xth[(size_t)KTOT * BB];   // x^T hi, k-major [K][B]
__device__ __nv_bfloat16 g_xtl[(size_t)KTOT * BB];   // x^T lo
__device__ __nv_bfloat16 g_w1h[(size_t)KTOT * HH];
__device__ __nv_bfloat16 g_w1l[(size_t)KTOT * HH];
__device__ __nv_bfloat16 g_w2h[(size_t)KTOT * HH];
__device__ __nv_bfloat16 g_w2l[(size_t)KTOT * HH];
__device__ int g_cnt[3];
__device__ int g_k;

// ---------------------------------------------------------------------------
// helpers
// ---------------------------------------------------------------------------
__device__ __forceinline__ uint32_t smem_u32(const void* p) {
    uint32_t a;
    asm("{ .reg .u64 t; cvta.to.shared.u64 t, %1; cvt.u32.u64 %0, t; }" : "=r"(a) : "l"(p));
    return a;
}

#define CPA16(dst, src) \
    asm volatile("cp.async.cg.shared.global [%0], [%1], 16;" :: "r"(dst), "l"(src))
#define CPA_COMMIT() asm volatile("cp.async.commit_group;" ::: "memory")

#define LDSM4T(r0, r1, r2, r3, addr) \
    asm volatile("ldmatrix.sync.aligned.m8n8.x4.trans.shared.b16 {%0,%1,%2,%3}, [%4];" \
                 : "=r"(r0), "=r"(r1), "=r"(r2), "=r"(r3) : "r"(addr) : "memory")

#define MMA16816(d, a, b0, b1) \
    asm volatile("mma.sync.aligned.m16n8k16.row.col.f32.bf16.bf16.f32 " \
                 "{%0,%1,%2,%3}, {%4,%5,%6,%7}, {%8,%9}, {%0,%1,%2,%3};" \
                 : "+f"((d)[0]), "+f"((d)[1]), "+f"((d)[2]), "+f"((d)[3]) \
                 : "r"((a)[0]), "r"((a)[1]), "r"((a)[2]), "r"((a)[3]), \
                   "r"(b0), "r"(b1))

// ---------------------------------------------------------------------------
// split + transpose x: [B, D] fp32 -> xT hi/lo bf16 [KTOT][B]; zero k>=2048
// ---------------------------------------------------------------------------
__global__ void split_xT_kernel(const float* __restrict__ x,
                                __nv_bfloat16* __restrict__ xh,
                                __nv_bfloat16* __restrict__ xl)
{
    __shared__ float t[32][33];
    int k0 = blockIdx.x * 32, m0 = blockIdx.y * 32;
    int tx = threadIdx.x, ty = threadIdx.y;     // 32 x 8
    if (k0 < DD) {
#pragma unroll
        for (int i = ty; i < 32; i += 8)
            t[i][tx] = x[(size_t)(m0 + i) * DD + k0 + tx];
    }
    __syncthreads();
#pragma unroll
    for (int i = ty; i < 32; i += 8) {
        int k = k0 + i;
        float v = (k0 < DD) ? t[tx][i] : 0.0f;
        __nv_bfloat16 h = __float2bfloat16(v);
        xh[(size_t)k * BB + m0 + tx] = h;
        xl[(size_t)k * BB + m0 + tx] = __float2bfloat16(v - __bfloat162float(h));
    }
}

// ---------------------------------------------------------------------------
// split W: [Klim, 1024] fp32 -> hi/lo bf16 [KTOT][1024], zero past Klim
// ---------------------------------------------------------------------------
__global__ void split_w_kernel(const float* __restrict__ W, int Klim,
                               __nv_bfloat16* __restrict__ wh,
                               __nv_bfloat16* __restrict__ wl)
{
    int idx = blockIdx.x * 256 + threadIdx.x;   // over KTOT*1024
    int k = idx >> 10, n = idx & 1023;
    float v = (k < Klim) ? W[(size_t)k * HH + n] : 0.0f;
    __nv_bfloat16 h = __float2bfloat16(v);
    wh[idx] = h;
    wl[idx] = __float2bfloat16(v - __bfloat162float(h));
}

// ---------------------------------------------------------------------------
// HMMA split-bf16 GEMM: C[M,1024] = relu(A^T-tiles @ W + bias)
// A: k-major [K][16384] bf16 hi/lo. W: k-major [K][1024] bf16 hi/lo.
// CTA tile 128x128, BK=32, 8 warps (2m x 4n), each warp 64x32.
// ---------------------------------------------------------------------------
#define STG_BYTES 32768
#define GEMM_SMEM (2 * STG_BYTES + 1024)

__device__ __forceinline__ void gemm_ld_stage(
    uint32_t db, int s, int c,
    const __nv_bfloat16* __restrict__ Ah, const __nv_bfloat16* __restrict__ Al,
    const __nv_bfloat16* __restrict__ Wh, const __nv_bfloat16* __restrict__ Wl,
    int m0, int n0, int tid)
{
    int k  = tid >> 3;                 // 0..31
    int mc = (tid & 7) * 2;            // chunk pair
    uint32_t base = db + s * STG_BYTES;
    uint32_t d0 = k * 256 + ((mc ^ (k & 7)) << 4);
    uint32_t d1 = k * 256 + (((mc + 1) ^ (k & 7)) << 4);
    size_t ka = (size_t)(c * 32 + k);
    const char* pah = (const char*)(Ah + ka * BB + m0 + mc * 8);
    const char* pal = (const char*)(Al + ka * BB + m0 + mc * 8);
    const char* pwh = (const char*)(Wh + ka * HH + n0 + mc * 8);
    const char* pwl = (const char*)(Wl + ka * HH + n0 + mc * 8);
    CPA16(base + d0,         pah);      CPA16(base + d1,         pah + 16);
    CPA16(base + 8192  + d0, pal);      CPA16(base + 8192  + d1, pal + 16);
    CPA16(base + 16384 + d0, pwh);      CPA16(base + 16384 + d1, pwh + 16);
    CPA16(base + 24576 + d0, pwl);      CPA16(base + 24576 + d1, pwl + 16);
    CPA_COMMIT();
}

__global__ __launch_bounds__(256, 1)
void gemm_mma(const __nv_bfloat16* __restrict__ Ah, const __nv_bfloat16* __restrict__ Al,
              const __nv_bfloat16* __restrict__ Wh, const __nv_bfloat16* __restrict__ Wl,
              const float* __restrict__ bias, float* __restrict__ C, int nch)
{
    extern __shared__ char smem[];
    uint32_t db = (smem_u32(smem) + 1023) & ~1023u;
    int tid = threadIdx.x, lane = tid & 31, wid = tid >> 5;
    int wm = wid >> 2, wn = wid & 3;
    int m0 = blockIdx.y * 128, n0 = blockIdx.x * 128;

    // precompute per-lane ldmatrix offsets (stage/ks-invariant)
    int q = lane >> 3, r = lane & 7;
    int kq = ((q >> 1) << 3) + r;       // 0..15
    int sw = kq & 7;
    uint32_t offA[4], offB[2];
#pragma unroll
    for (int mt = 0; mt < 4; ++mt) {
        int cc = wm * 8 + mt * 2 + (q & 1);
        offA[mt] = kq * 256 + ((cc ^ sw) << 4);
    }
#pragma unroll
    for (int bt = 0; bt < 2; ++bt) {
        int cc = wn * 4 + bt * 2 + (q & 1);
        offB[bt] = kq * 256 + ((cc ^ sw) << 4);
    }

    float acc[4][4][4] = {};

    gemm_ld_stage(db, 0, 0, Ah, Al, Wh, Wl, m0, n0, tid);

    for (int c = 0; c < nch; ++c) {
        if (c + 1 < nch) {
            gemm_ld_stage(db, (c + 1) & 1, c + 1, Ah, Al, Wh, Wl, m0, n0, tid);
            asm volatile("cp.async.wait_group 1;" ::: "memory");
        } else {
            asm volatile("cp.async.wait_group 0;" ::: "memory");
        }
        __syncthreads();

        uint32_t sbase = db + (c & 1) * STG_BYTES;
#pragma unroll
        for (int ks = 0; ks < 2; ++ks) {
            uint32_t sb = sbase + ks * 4096;
            uint32_t ah[4][4], al_[4][4], bh_[2][4], bl_[2][4];
#pragma unroll
            for (int mt = 0; mt < 4; ++mt) {
                LDSM4T(ah[mt][0],  ah[mt][1],  ah[mt][2],  ah[mt][3],  sb + offA[mt]);
                LDSM4T(al_[mt][0], al_[mt][1], al_[mt][2], al_[mt][3], sb + 8192 + offA[mt]);
            }
#pragma unroll
            for (int bt = 0; bt < 2; ++bt) {
                LDSM4T(bh_[bt][0], bh_[bt][1], bh_[bt][2], bh_[bt][3], sb + 16384 + offB[bt]);
                LDSM4T(bl_[bt][0], bl_[bt][1], bl_[bt][2], bl_[bt][3], sb + 24576 + offB[bt]);
            }
            // term 1: Ah * Wh
#pragma unroll
            for (int mt = 0; mt < 4; ++mt)
#pragma unroll
                for (int nt = 0; nt < 4; ++nt) {
                    int bt = nt >> 1, p = nt & 1;
                    MMA16816(acc[mt][nt], ah[mt], bh_[bt][p], bh_[bt][p + 2]);
                }
            // term 2: Ah * Wl
#pragma unroll
            for (int mt = 0; mt < 4; ++mt)
#pragma unroll
                for (int nt = 0; nt < 4; ++nt) {
                    int bt = nt >> 1, p = nt & 1;
                    MMA16816(acc[mt][nt], ah[mt], bl_[bt][p], bl_[bt][p + 2]);
                }
            // term 3: Al * Wh
#pragma unroll
            for (int mt = 0; mt < 4; ++mt)
#pragma unroll
                for (int nt = 0; nt < 4; ++nt) {
                    int bt = nt >> 1, p = nt & 1;
                    MMA16816(acc[mt][nt], al_[mt], bh_[bt][p], bh_[bt][p + 2]);
                }
        }
        __syncthreads();
    }

    // epilogue: bias + relu, direct stores
    int g = lane >> 2, t2 = (lane & 3) * 2;
#pragma unroll
    for (int nt = 0; nt < 4; ++nt) {
        int col = n0 + wn * 32 + nt * 8 + t2;
        float2 bv = *(const float2*)(bias + col);
#pragma unroll
        for (int mt = 0; mt < 4; ++mt) {
            int row = m0 + wm * 64 + mt * 16 + g;
            float2 o0, o1;
            o0.x = fmaxf(acc[mt][nt][0] + bv.x, 0.f);
            o0.y = fmaxf(acc[mt][nt][1] + bv.y, 0.f);
            o1.x = fmaxf(acc[mt][nt][2] + bv.x, 0.f);
            o1.y = fmaxf(acc[mt][nt][3] + bv.y, 0.f);
            *(float2*)(C + (size_t)row * HH + col) = o0;
            *(float2*)(C + (size_t)(row + 8) * HH + col) = o1;
        }
    }
}

// ---------------------------------------------------------------------------
// block reduce (256 threads)
// ---------------------------------------------------------------------------
__device__ __forceinline__ float block_reduce(float v, float* red, bool ismax)
{
    int tid = threadIdx.x;
#pragma unroll
    for (int o = 16; o; o >>= 1) {
        float t = __shfl_down_sync(0xffffffffu, v, o);
        v = ismax ? fmaxf(v, t) : (v + t);
    }
    if ((tid & 31) == 0) red[tid >> 5] = v;
    __syncthreads();
    if (tid < 32) {
        float t2 = (tid < 8) ? red[tid] : (ismax ? -3.4e38f : 0.0f);
#pragma unroll
        for (int o = 4; o; o >>= 1) {
            float t = __shfl_down_sync(0xffffffffu, t2, o);
            t2 = ismax ? fmaxf(t2, t) : (t2 + t);
        }
        if (tid == 0) red[0] = t2;
    }
    __syncthreads();
    float r = red[0];
    __syncthreads();
    return r;
}

// ---------------------------------------------------------------------------
// Stats kernel: moments + exact top-409 |x| sum via 4-pass radix select
// ---------------------------------------------------------------------------
__global__ void stats_kernel(const float* __restrict__ x, float* __restrict__ stats)
{
    __shared__ float sx[2048];
    __shared__ float red[8];
    __shared__ int hist[256];
    __shared__ int scan[256];
    __shared__ unsigned s_pref;
    __shared__ int s_need;

    int row = blockIdx.x;
    int tid = threadIdx.x;

    const float4* xr = (const float4*)(x + (size_t)row * DD);
    float4* sx4 = (float4*)sx;
    for (int i = tid; i < 512; i += 256) sx4[i] = xr[i];
    __syncthreads();

    float sum = 0.f, sumsq = 0.f, maxa = 0.f, suma = 0.f, zc = 0.f;
    for (int i = tid; i < 2048; i += 256) {
        float v = sx[i];
        sum += v; sumsq += v * v;
        float a = fabsf(v);
        suma += a; maxa = fmaxf(maxa, a);
        zc += (v == 0.0f) ? 1.f : 0.f;
    }
    sum   = block_reduce(sum,   red, false);
    sumsq = block_reduce(sumsq, red, false);
    suma  = block_reduce(suma,  red, false);
    zc    = block_reduce(zc,    red, false);
    maxa  = block_reduce(maxa,  red, true);

    float mean = sum * (1.0f / 2048.0f);
    float s2 = 0.f, s3 = 0.f;
    for (int i = tid; i < 2048; i += 256) {
        float d = sx[i] - mean;
        s2 += d * d;
        s3 += d * d * d;
    }
    s2 = block_reduce(s2, red, false);
    s3 = block_reduce(s3, red, false);
    float var  = s2 * (1.0f / 2047.0f);
    float stdv = sqrtf(var + 1e-8f);
    float skew = (s3 * (1.0f / 2048.0f)) / (stdv * stdv * stdv);

    unsigned prefix = 0;
    int need = TOPC;
#pragma unroll
    for (int pass = 0; pass < 4; ++pass) {
        int shift = 24 - 8 * pass;
        hist[tid] = 0;
        __syncthreads();
        for (int i = tid; i < 2048; i += 256) {
            unsigned b = __float_as_uint(sx[i]) & 0x7fffffffu;
            bool match = (pass == 0) || ((b >> (shift + 8)) == prefix);
            if (match) atomicAdd(&hist[(b >> shift) & 255], 1);
        }
        __syncthreads();
        scan[tid] = hist[tid];
        __syncthreads();
        for (int off = 1; off < 256; off <<= 1) {
            int v2 = (tid + off < 256) ? scan[tid + off] : 0;
            __syncthreads();
            scan[tid] += v2;
            __syncthreads();
        }
        int incl = scan[tid];
        int excl = incl - hist[tid];
        if (excl < need && need <= incl) {
            s_pref = (prefix << 8) | (unsigned)tid;
            s_need = need - excl;
        }
        __syncthreads();
        prefix = s_pref;
        need = s_need;
        __syncthreads();
    }

    unsigned tb = prefix;
    float tval = __uint_as_float(tb);
    float tsum = 0.f;
    for (int i = tid; i < 2048; i += 256) {
        unsigned b = __float_as_uint(sx[i]) & 0x7fffffffu;
        if (b > tb) tsum += __uint_as_float(b);
    }
    tsum = block_reduce(tsum, red, false);
    tsum += (float)need * tval;

    if (tid == 0) {
        float* o = stats + (size_t)row * 6;
        o[0] = zc * (1.0f / 2048.0f);
        o[1] = var;
        o[2] = maxa;
        o[3] = sqrtf(sumsq);
        o[4] = skew;
        o[5] = tsum / (suma + 1e-8f);
    }
}

// ---------------------------------------------------------------------------
// spec kernel: spec = sigmoid(x@patterns^T + h1@Ws2 + bs2); also writes
// bf16 split of spec into xT rows [2048, 2064)
// ---------------------------------------------------------------------------
__global__ void spec_kernel(const float* __restrict__ x, const float* __restrict__ pat,
                            const float* __restrict__ h1, const float* __restrict__ Ws2,
                            const float* __restrict__ bs2, float* __restrict__ spec,
                            __nv_bfloat16* __restrict__ xth, __nv_bfloat16* __restrict__ xtl)
{
    __shared__ float xs[64][68];
    __shared__ float ws[64][16];
    int tid = threadIdx.x;
    int row0 = blockIdx.x * 64;
    int e = tid & 15;
    int r0 = (tid >> 4) * 4;
    float acc[4] = {};

    for (int kc = 0; kc < DD; kc += 64) {
#pragma unroll
        for (int it = 0; it < 4; ++it) {
            int idx = tid + it * 256;
            int r = idx >> 4, c4 = idx & 15;
            *(float4*)&xs[r][c4 * 4] =
                *(const float4*)(x + (size_t)(row0 + r) * DD + kc + c4 * 4);
        }
        {
            int pe = tid & 15, k4 = tid >> 4;
            float4 v = *(const float4*)(pat + (size_t)pe * DD + kc + k4 * 4);
            ws[k4 * 4 + 0][pe] = v.x; ws[k4 * 4 + 1][pe] = v.y;
            ws[k4 * 4 + 2][pe] = v.z; ws[k4 * 4 + 3][pe] = v.w;
        }
        __syncthreads();
#pragma unroll 4
        for (int k = 0; k < 64; ++k) {
            float w = ws[k][e];
            acc[0] += xs[r0 + 0][k] * w;
            acc[1] += xs[r0 + 1][k] * w;
            acc[2] += xs[r0 + 2][k] * w;
            acc[3] += xs[r0 + 3][k] * w;
        }
        __syncthreads();
    }
    for (int kc = 0; kc < HH; kc += 64) {
#pragma unroll
        for (int it = 0; it < 4; ++it) {
            int idx = tid + it * 256;
            int r = idx >> 4, c4 = idx & 15;
            *(float4*)&xs[r][c4 * 4] =
                *(const float4*)(h1 + (size_t)(row0 + r) * HH + kc + c4 * 4);
        }
        {
            int k = tid >> 2, e4 = tid & 3;
            *(float4*)&ws[k][e4 * 4] =
                *(const float4*)(Ws2 + (size_t)(kc + k) * EE + e4 * 4);
        }
        __syncthreads();
#pragma unroll 4
        for (int k = 0; k < 64; ++k) {
            float w = ws[k][e];
            acc[0] += xs[r0 + 0][k] * w;
            acc[1] += xs[r0 + 1][k] * w;
            acc[2] += xs[r0 + 2][k] * w;
            acc[3] += xs[r0 + 3][k] * w;
        }
        __syncthreads();
    }
    float b = bs2[e];
#pragma unroll
    for (int j = 0; j < 4; ++j) {
        float v = acc[j] + b;
        float sg = 1.0f / (1.0f + expf(-v));
        size_t row = (size_t)(row0 + r0 + j);
        spec[row * EE + e] = sg;
        __nv_bfloat16 h = __float2bfloat16(sg);
        xth[(size_t)(DD + e) * BB + row] = h;
        xtl[(size_t)(DD + e) * BB + row] = __float2bfloat16(sg - __bfloat162float(h));
    }
}

// ---------------------------------------------------------------------------
// probs kernel: probs = softmax(h2 @ Wr2 + br2)
// ---------------------------------------------------------------------------
__global__ void probs_kernel(const float* __restrict__ h2, const float* __restrict__ Wr2,
                             const float* __restrict__ br2, float* __restrict__ probs)
{
    __shared__ float xs[64][68];
    __shared__ float ws[64][16];
    __shared__ float lg[64][17];
    int tid = threadIdx.x;
    int row0 = blockIdx.x * 64;
    int e = tid & 15;
    int r0 = (tid >> 4) * 4;
    float acc[4] = {};

    for (int kc = 0; kc < HH; kc += 64) {
#pragma unroll
        for (int it = 0; it < 4; ++it) {
            int idx = tid + it * 256;
            int r = idx >> 4, c4 = idx & 15;
            *(float4*)&xs[r][c4 * 4] =
                *(const float4*)(h2 + (size_t)(row0 + r) * HH + kc + c4 * 4);
        }
        {
            int k = tid >> 2, e4 = tid & 3;
            *(float4*)&ws[k][e4 * 4] =
                *(const float4*)(Wr2 + (size_t)(kc + k) * EE + e4 * 4);
        }
        __syncthreads();
#pragma unroll 4
        for (int k = 0; k < 64; ++k) {
            float w = ws[k][e];
            acc[0] += xs[r0 + 0][k] * w;
            acc[1] += xs[r0 + 1][k] * w;
            acc[2] += xs[r0 + 2][k] * w;
            acc[3] += xs[r0 + 3][k] * w;
        }
        __syncthreads();
    }
    float b = br2[e];
#pragma unroll
    for (int j = 0; j < 4; ++j) lg[r0 + j][e] = acc[j] + b;
    __syncthreads();

    if (tid < 64) {
        int r = tid;
        float m = -3.4e38f;
#pragma unroll
        for (int k = 0; k < 16; ++k) m = fmaxf(m, lg[r][k]);
        float pv[16]; float s = 0.f;
#pragma unroll
        for (int k = 0; k < 16; ++k) { pv[k] = expf(lg[r][k] - m); s += pv[k]; }
        float inv = 1.0f / s;
        float* o = probs + (size_t)(row0 + r) * EE;
#pragma unroll
        for (int k = 0; k < 16; ++k) o[k] = pv[k] * inv;
    }
}

// ---------------------------------------------------------------------------
// k predictor + median decision + top-k
// ---------------------------------------------------------------------------
__global__ void kpred_kernel(const float* __restrict__ stats, const float* __restrict__ Wk1,
                             const float* __restrict__ bk1, const float* __restrict__ Wk2,
                             const float* __restrict__ bk2)
{
    int row = blockIdx.x * 256 + threadIdx.x;
    float s[6];
#pragma unroll
    for (int i = 0; i < 6; ++i) s[i] = stats[(size_t)row * 6 + i];
    float o = bk2[0];
#pragma unroll
    for (int h = 0; h < 16; ++h) {
        float z = bk1[h];
#pragma unroll
        for (int i = 0; i < 6; ++i) z += s[i] * Wk1[i * 16 + h];
        o += fmaxf(z, 0.f) * Wk2[h];
    }
    float kv = 1.0f / (1.0f + expf(-o));
    float val = 1.0f + 3.0f * kv;
    unsigned b2 = __ballot_sync(0xffffffffu, val < 2.0f);
    unsigned b3 = __ballot_sync(0xffffffffu, val < 3.0f);
    unsigned b4 = __ballot_sync(0xffffffffu, val < 4.0f);
    if ((threadIdx.x & 31) == 0) {
        atomicAdd(&g_cnt[0], __popc(b2));
        atomicAdd(&g_cnt[1], __popc(b3));
        atomicAdd(&g_cnt[2], __popc(b4));
    }
}

__global__ void init_kernel() { g_cnt[0] = 0; g_cnt[1] = 0; g_cnt[2] = 0; }

__global__ void kdecide_kernel()
{
    int k;
    if (g_cnt[0] >= 8192)      k = 1;
    else if (g_cnt[1] >= 8192) k = 2;
    else if (g_cnt[2] >= 8192) k = 3;
    else                       k = 4;
    g_k = k;
}

__global__ void topk_kernel(const float* __restrict__ probs,
                            float* __restrict__ gates, float* __restrict__ idxo)
{
    int row = blockIdx.x * 256 + threadIdx.x;
    float p[16];
    const float4* pr = (const float4*)(probs + (size_t)row * EE);
    ((float4*)p)[0] = pr[0]; ((float4*)p)[1] = pr[1];
    ((float4*)p)[2] = pr[2]; ((float4*)p)[3] = pr[3];

    unsigned used = 0;
    float tv[4]; int ti[4];
#pragma unroll
    for (int s = 0; s < 4; ++s) {
        float bv = -1.0f; int bi = 0;
#pragma unroll
        for (int e = 0; e < 16; ++e) {
            bool ok = (((used >> e) & 1u) == 0u) && (p[e] > bv);
            if (ok) { bv = p[e]; bi = e; }
        }
        used |= (1u << bi);
        tv[s] = bv; ti[s] = bi;
    }
    int k = g_k;
    float g[4]; float ssum = 0.f;
#pragma unroll
    for (int j = 0; j < 4; ++j) {
        g[j] = (j < k) ? expf(tv[j] - tv[0]) : 0.0f;
        ssum += g[j];
    }
    float inv = 1.0f / ssum;
#pragma unroll
    for (int j = 0; j < 4; ++j) {
        gates[(size_t)row * 4 + j] = g[j] * inv;
        idxo[(size_t)row * 4 + j] = (float)ti[j];
    }
}

// ---------------------------------------------------------------------------
extern "C" void kernel_launch(void* const* d_in, const int* in_sizes, int n_in,
                              void* d_out, int out_size)
{
    const float* x    = (const float*)d_in[0];
    const float* pat  = (const float*)d_in[1];
    const float* Ws1  = (const float*)d_in[2];
    const float* bs1  = (const float*)d_in[3];
    const float* Ws2  = (const float*)d_in[4];
    const float* bs2  = (const float*)d_in[5];
    const float* Wr1  = (const float*)d_in[6];
    const float* br1  = (const float*)d_in[7];
    const float* Wr2  = (const float*)d_in[8];
    const float* br2  = (const float*)d_in[9];
    const float* Wk1  = (const float*)d_in[10];
    const float* bk1  = (const float*)d_in[11];
    const float* Wk2  = (const float*)d_in[12];
    const float* bk2  = (const float*)d_in[13];

    float* out = (float*)d_out;
    float* o_gates = out;                      // 16384*4
    float* o_idx   = out + 65536;              // 16384*4
    float* o_probs = out + 131072;             // 16384*16
    float* o_stats = out + 393216;             // 16384*6

    void* p;
    cudaGetSymbolAddress(&p, g_h1);   float* h1 = (float*)p;
    cudaGetSymbolAddress(&p, g_h2);   float* h2 = (float*)p;
    cudaGetSymbolAddress(&p, g_spec); float* spec = (float*)p;
    cudaGetSymbolAddress(&p, g_xth);  __nv_bfloat16* xth = (__nv_bfloat16*)p;
    cudaGetSymbolAddress(&p, g_xtl);  __nv_bfloat16* xtl = (__nv_bfloat16*)p;
    cudaGetSymbolAddress(&p, g_w1h);  __nv_bfloat16* w1h = (__nv_bfloat16*)p;
    cudaGetSymbolAddress(&p, g_w1l);  __nv_bfloat16* w1l = (__nv_bfloat16*)p;
    cudaGetSymbolAddress(&p, g_w2h);  __nv_bfloat16* w2h = (__nv_bfloat16*)p;
    cudaGetSymbolAddress(&p, g_w2l);  __nv_bfloat16* w2l = (__nv_bfloat16*)p;

    cudaFuncSetAttribute(gemm_mma, cudaFuncAttributeMaxDynamicSharedMemorySize, GEMM_SMEM);

    // input conversions
    {
        dim3 tb(32, 8);
        dim3 tg(KTOT / 32, BB / 32);
        split_xT_kernel<<<tg, tb>>>(x, xth, xtl);
    }
    split_w_kernel<<<(KTOT * HH) / 256, 256>>>(Ws1, DD, w1h, w1l);
    split_w_kernel<<<(KTOT * HH) / 256, 256>>>(Wr1, DD + EE, w2h, w2l);

    // stats + dynamic-k chain
    stats_kernel<<<BB, 256>>>(x, o_stats);
    init_kernel<<<1, 1>>>();
    kpred_kernel<<<BB / 256, 256>>>(o_stats, Wk1, bk1, Wk2, bk2);
    kdecide_kernel<<<1, 1>>>();

    dim3 gg(HH / 128, BB / 128);
    // h1 = relu(x @ Ws1 + bs1), K = 2048 -> 64 chunks
    gemm_mma<<<gg, 256, GEMM_SMEM>>>(xth, xtl, w1h, w1l, bs1, h1, 64);

    // spec = sigmoid(x@pat^T + h1@Ws2 + bs2); writes bf16 split into xT tail
    spec_kernel<<<BB / 64, 256>>>(x, pat, h1, Ws2, bs2, spec, xth, xtl);

    // h2 = relu([x, spec] @ Wr1 + br1), K = 2080 (zero-padded) -> 65 chunks
    gemm_mma<<<gg, 256, GEMM_SMEM>>>(xth, xtl, w2h, w2l, br1, h2, 65);

    // probs = softmax(h2 @ Wr2 + br2)
    probs_kernel<<<BB / 64, 256>>>(h2, Wr2, br2, o_probs);

    // gates + indices
    topk_kernel<<<BB / 256, 256>>>(o_probs, o_gates, o_idx);

    (void)in_sizes; (void)n_in; (void)out_size;
}